// round 10
// baseline (speedup 1.0000x reference)
#include <cuda_runtime.h>
#include <math.h>

#define BB 32
#define DIM 4096
#define NH 32
#define NKV 8
#define GQ 4
#define HD 128
#define KVLEN 4096
#define QKVC 6144          // (NH + 2*NKV) * HD
#define KSPLIT 32          // K-dim split for GEMMs (grid parallelism)
#define KCH 128            // K chunk per block (DIM / KSPLIT)
#define CHUNK 256          // KV positions per attention split
#define NSPLIT 16          // KVLEN / CHUNK

// packed fp32x2 FMA (sm_100+): 2x FLOP per issue slot vs FFMA
#define FMA_F32X2(d, a, b, c) \
    asm("fma.rn.f32x2 %0, %1, %2, %3;" : "=l"(d) : "l"(a), "l"(b), "l"(c))

// ---------------- scratch (no allocs allowed) ----------------
__device__ float g_part1[KSPLIT][BB][QKVC];     // qkv gemm partials (25 MB)
__device__ float g_part2[KSPLIT][BB][DIM];      // out gemm partials (17 MB)
__device__ float g_q[BB * NH * HD];             // rope'd q
__device__ float g_knew[BB * NKV * HD];         // rope'd new k
__device__ float g_vnew[BB * NKV * HD];         // new v
__device__ float g_pm[BB * NKV * NSPLIT * GQ];  // partial max
__device__ float g_ps[BB * NKV * NSPLIT * GQ];  // partial sumexp
__device__ float g_pacc[BB * NKV * NSPLIT * GQ * HD]; // partial weighted V
__device__ float g_attn[BB * DIM];              // attention output (pre-wo)

// ---------------- GEMM partial: 2 columns/thread, f32x2 FMA ----------------
// Each thread computes 32 batches x 2 columns (c, c+256). 8 LDS.128 feed 32
// FFMA2 per K-step. grid (COLS/512, KSPLIT), block 256.
template <int COLS>
__global__ void __launch_bounds__(256) k_gemm_part(const float* __restrict__ x,
                                                   const float* __restrict__ w,
                                                   float* __restrict__ part) {
    __shared__ float xs[KCH][BB];  // transposed x tile, 16 KB
    const int c0 = blockIdx.x * 512 + threadIdx.x;  // second col = c0 + 256
    const int d0 = blockIdx.y * KCH;
    for (int i = threadIdx.x; i < KCH * BB; i += 256) {
        int dd = i >> 5, b = i & 31;
        xs[dd][b] = x[b * DIM + d0 + dd];
    }
    __syncthreads();
    unsigned long long accA[16], accB[16];  // 32 batch accums per column
#pragma unroll
    for (int i = 0; i < 16; i++) { accA[i] = 0ull; accB[i] = 0ull; }

    const float* wcol = w + (size_t)d0 * COLS + c0;
    float wva[4], wvb[4];
#pragma unroll
    for (int u = 0; u < 4; u++) {  // 8 LDGs in flight
        wva[u] = wcol[(size_t)u * COLS];
        wvb[u] = wcol[(size_t)u * COLS + 256];
    }

    for (int g = 0; g < KCH; g += 4) {
        float wna[4], wnb[4];
        if (g + 4 < KCH) {
            const float* wnp = wcol + (size_t)(g + 4) * COLS;
#pragma unroll
            for (int u = 0; u < 4; u++) {
                wna[u] = wnp[(size_t)u * COLS];
                wnb[u] = wnp[(size_t)u * COLS + 256];
            }
        } else {
#pragma unroll
            for (int u = 0; u < 4; u++) { wna[u] = 0.f; wnb[u] = 0.f; }
        }
#pragma unroll
        for (int u = 0; u < 4; u++) {
            unsigned long long w2a, w2b;
            asm("mov.b64 %0, {%1, %1};" : "=l"(w2a) : "f"(wva[u]));
            asm("mov.b64 %0, {%1, %1};" : "=l"(w2b) : "f"(wvb[u]));
            const ulonglong2* xr = (const ulonglong2*)xs[g + u];
#pragma unroll
            for (int j = 0; j < 8; j++) {
                ulonglong2 xv = xr[j];  // LDS.128 broadcast: 4 batches
                FMA_F32X2(accA[2 * j + 0], xv.x, w2a, accA[2 * j + 0]);
                FMA_F32X2(accA[2 * j + 1], xv.y, w2a, accA[2 * j + 1]);
                FMA_F32X2(accB[2 * j + 0], xv.x, w2b, accB[2 * j + 0]);
                FMA_F32X2(accB[2 * j + 1], xv.y, w2b, accB[2 * j + 1]);
            }
        }
#pragma unroll
        for (int u = 0; u < 4; u++) { wva[u] = wna[u]; wvb[u] = wnb[u]; }
    }

    float* o = part + (size_t)blockIdx.y * BB * COLS + c0;
#pragma unroll
    for (int i = 0; i < 16; i++) {
        float lo, hi;
        asm("mov.b64 {%0, %1}, %2;" : "=f"(lo), "=f"(hi) : "l"(accA[i]));
        o[(size_t)(2 * i) * COLS] = lo;
        o[(size_t)(2 * i + 1) * COLS] = hi;
        asm("mov.b64 {%0, %1}, %2;" : "=f"(lo), "=f"(hi) : "l"(accB[i]));
        o[(size_t)(2 * i) * COLS + 256] = lo;
        o[(size_t)(2 * i + 1) * COLS + 256] = hi;
    }
}

// ---------------- reduce qkv partials + rope ----------------
__global__ void __launch_bounds__(128) k_reduce_rope(const float* __restrict__ rot) {
    const int b = blockIdx.x / 48;
    const int h = blockIdx.x % 48;
    const int t = threadIdx.x;
    float s = 0.f;
#pragma unroll
    for (int p = 0; p < KSPLIT; p++) s += g_part1[p][b][h * HD + t];
    if (h >= 40) {  // v: no rope (uniform per block)
        g_vnew[(b * NKV + (h - 40)) * HD + t] = s;
        return;
    }
    __shared__ float vsh[HD];
    vsh[t] = s;
    __syncthreads();
    float o = 0.f;
#pragma unroll 8
    for (int d = 0; d < HD; d++) o = fmaf(vsh[d], rot[d * HD + t], o);
    if (h < 32)
        g_q[(b * NH + h) * HD + t] = o;
    else
        g_knew[(b * NKV + (h - 32)) * HD + t] = o;
}

// ---------------- dummy: shifts the qkv GEMM into the ncu-profiled slot ----
__global__ void k_dummy() {}

// ---------------- flash-decode partial attention (256 threads) ----------------
// R7 version (measured 143us): 8 lanes per KV row, 4 rows per warp, coalesced
// LDG.128, depth-4 K prefetch. No min-blocks cap (caps cause local spills).
__global__ void __launch_bounds__(256) k_attn_part(const float* __restrict__ ck,
                                                   const float* __restrict__ cv,
                                                   const int* __restrict__ curp) {
    const int bk = blockIdx.x;  // b*NKV + kv
    const int b = bk >> 3, kv = bk & 7;
    const int sp = blockIdx.y;
    const int cur = *curp;
    const int L = cur + 1;
    const int s0 = sp * CHUNK;
    const int scnt = min(CHUNK, L - s0);
    if (scnt <= 0) return;
    const int pbase = (bk * NSPLIT + sp) * GQ;
    const int t = threadIdx.x;
    const bool has_cur = (s0 + CHUNK >= L);  // cur at s = scnt-1 of last split

    __shared__ float4 sc4[CHUNK];        // probs, transposed: sc4[s]={h0..h3}
    __shared__ float4 qsh[GQ][HD / 4];
    __shared__ float red[8];
    __shared__ float mh[GQ], sumh[GQ];
    __shared__ float vred[GQ][HD];       // V-stage cross-half reduce

    ((float2*)qsh)[t] = ((const float2*)(g_q + (b * NH + kv * GQ) * HD))[t];
    __syncthreads();

    const float scale = 0.08838834764831845f;  // 1/sqrt(128)
    const float* kbase = ck + (size_t)(b * NKV + kv) * KVLEN * HD;

    // ---- scores: warp covers 4 rows, 8 lanes per row (coalesced LDG.128) ----
    {
        const int lane = t & 31, w = t >> 5;
        const int d8 = lane & 7;   // float4 column slot within row
        const int r4 = lane >> 3;  // row within the 4-row group
        for (int g = w; g < CHUNK / 4; g += 8) {
            const int s = g * 4 + r4;
            const bool act = (s < scnt);
            ulonglong2 k4[4];
#pragma unroll
            for (int j = 0; j < 4; j++) { k4[j].x = 0ull; k4[j].y = 0ull; }
            if (act) {
                const ulonglong2* kr = (has_cur && s == scnt - 1)
                    ? (const ulonglong2*)(g_knew + (b * NKV + kv) * HD)
                    : (const ulonglong2*)(kbase + (size_t)(s0 + s) * HD);
#pragma unroll
                for (int j = 0; j < 4; j++) k4[j] = kr[d8 + 8 * j];  // MLP=4
            }
            unsigned long long acc[4] = {0ull, 0ull, 0ull, 0ull};
#pragma unroll
            for (int j = 0; j < 4; j++) {
#pragma unroll
                for (int h = 0; h < 4; h++) {
                    ulonglong2 q2 = ((const ulonglong2*)qsh[h])[d8 + 8 * j];  // LDS.128
                    FMA_F32X2(acc[h], k4[j].x, q2.x, acc[h]);
                    FMA_F32X2(acc[h], k4[j].y, q2.y, acc[h]);
                }
            }
            float r[4];
#pragma unroll
            for (int h = 0; h < 4; h++) {
                float lo, hi;
                asm("mov.b64 {%0, %1}, %2;" : "=f"(lo), "=f"(hi) : "l"(acc[h]));
                r[h] = lo + hi;
            }
            // reduce across the 8 lanes of this row (xor 1,2,4 stays in-group)
#pragma unroll
            for (int o = 1; o <= 4; o <<= 1) {
#pragma unroll
                for (int h = 0; h < 4; h++)
                    r[h] += __shfl_xor_sync(0xffffffffu, r[h], o);
            }
            if (act && d8 == 0)
                sc4[s] = make_float4(r[0] * scale, r[1] * scale,
                                     r[2] * scale, r[3] * scale);
        }
    }
    __syncthreads();

    // ---- softmax, 4 heads in parallel: 64 threads per head ----
    {
        const int h = t >> 6, l64 = t & 63, wid = t >> 5, lane = t & 31;
        const float* schf = (const float*)sc4;  // schf[s*4 + h]
        float lm = -INFINITY;
        for (int s = l64; s < scnt; s += 64) lm = fmaxf(lm, schf[s * 4 + h]);
#pragma unroll
        for (int o = 16; o > 0; o >>= 1) lm = fmaxf(lm, __shfl_xor_sync(0xffffffffu, lm, o));
        if (lane == 0) red[wid] = lm;
        __syncthreads();
        if (l64 == 0) mh[h] = fmaxf(red[2 * h], red[2 * h + 1]);
        __syncthreads();
        const float m = mh[h];
        float ls = 0.f;
        float* scw = (float*)sc4;
        for (int s = l64; s < scnt; s += 64) {
            float p = __expf(scw[s * 4 + h] - m);
            scw[s * 4 + h] = p;
            ls += p;
        }
#pragma unroll
        for (int o = 16; o > 0; o >>= 1) ls += __shfl_xor_sync(0xffffffffu, ls, o);
        if (lane == 0) red[wid] = ls;
        __syncthreads();
        if (l64 == 0) sumh[h] = red[2 * h] + red[2 * h + 1];
    }
    __syncthreads();

    // ---- p @ V: d = t&127, s over 2 halves; f32x2 FMA ----
    {
        const int d = t & 127, half = t >> 7;
        unsigned long long a01 = 0ull, a23 = 0ull;
        const float* vbase = cv + ((size_t)(b * NKV + kv) * KVLEN + s0) * HD + d;
        const int slim = scnt - (has_cur ? 1 : 0);
#pragma unroll 8
        for (int s = half; s < slim; s += 2) {
            float vv = vbase[(size_t)s * HD];
            ulonglong2 p = ((const ulonglong2*)sc4)[s];  // broadcast LDS.128
            unsigned long long v2;
            asm("mov.b64 %0, {%1, %1};" : "=l"(v2) : "f"(vv));
            FMA_F32X2(a01, p.x, v2, a01);
            FMA_F32X2(a23, p.y, v2, a23);
        }
        if (has_cur && ((scnt - 1) & 1) == half) {
            const int s = scnt - 1;
            float vv = g_vnew[(b * NKV + kv) * HD + d];
            ulonglong2 p = ((const ulonglong2*)sc4)[s];
            unsigned long long v2;
            asm("mov.b64 %0, {%1, %1};" : "=l"(v2) : "f"(vv));
            FMA_F32X2(a01, p.x, v2, a01);
            FMA_F32X2(a23, p.y, v2, a23);
        }
        float a0, a1, a2, a3;
        asm("mov.b64 {%0, %1}, %2;" : "=f"(a0), "=f"(a1) : "l"(a01));
        asm("mov.b64 {%0, %1}, %2;" : "=f"(a2), "=f"(a3) : "l"(a23));
        if (half == 1) {
            vred[0][d] = a0; vred[1][d] = a1; vred[2][d] = a2; vred[3][d] = a3;
        }
        __syncthreads();
        if (half == 0) {
            g_pacc[(pbase + 0) * HD + d] = a0 + vred[0][d];
            g_pacc[(pbase + 1) * HD + d] = a1 + vred[1][d];
            g_pacc[(pbase + 2) * HD + d] = a2 + vred[2][d];
            g_pacc[(pbase + 3) * HD + d] = a3 + vred[3][d];
        }
        if (t < GQ) {
            g_pm[pbase + t] = mh[t];
            g_ps[pbase + t] = sumh[t];
        }
    }
}

// ---------------- LSE merge across splits (length-aware, float4) ----------------
__global__ void __launch_bounds__(128) k_combine(const int* __restrict__ curp) {
    const int bk = blockIdx.x;
    const int b = bk >> 3, kv = bk & 7;
    const int t = threadIdx.x;
    const int h = t >> 5, d4 = t & 31;
    const int nsp = (*curp + CHUNK) / CHUNK;  // ceil(L/CHUNK)

    __shared__ float esh[GQ][NSPLIT];
    __shared__ float dens[GQ];
    if (d4 == 0) {
        float m = -INFINITY;
        for (int sp = 0; sp < nsp; sp++)
            m = fmaxf(m, g_pm[(bk * NSPLIT + sp) * GQ + h]);
        float den = 0.f;
        for (int sp = 0; sp < nsp; sp++) {
            float e = __expf(g_pm[(bk * NSPLIT + sp) * GQ + h] - m);
            esh[h][sp] = e;
            den += g_ps[(bk * NSPLIT + sp) * GQ + h] * e;
        }
        dens[h] = den;
    }
    __syncthreads();
    float4 num = make_float4(0.f, 0.f, 0.f, 0.f);
#pragma unroll 4
    for (int sp = 0; sp < nsp; sp++) {
        const float4* pa = (const float4*)(g_pacc + ((bk * NSPLIT + sp) * GQ + h) * HD);
        float4 v = pa[d4];
        float e = esh[h][sp];
        num.x = fmaf(v.x, e, num.x); num.y = fmaf(v.y, e, num.y);
        num.z = fmaf(v.z, e, num.z); num.w = fmaf(v.w, e, num.w);
    }
    const float inv = 1.0f / dens[h];
    float4* o = (float4*)(g_attn + (b * NH + kv * GQ + h) * HD);
    o[d4] = make_float4(num.x * inv, num.y * inv, num.z * inv, num.w * inv);
}

// ---------------- final reduce of out-gemm partials (float4) ----------------
__global__ void __launch_bounds__(256) k_out_reduce(float* __restrict__ out) {
    const int i = blockIdx.x * 256 + threadIdx.x;  // float4 index
    const float4* p2 = (const float4*)g_part2;
    float4 s = make_float4(0.f, 0.f, 0.f, 0.f);
#pragma unroll
    for (int p = 0; p < KSPLIT; p++) {
        float4 v = p2[(size_t)p * (BB * DIM / 4) + i];
        s.x += v.x; s.y += v.y; s.z += v.z; s.w += v.w;
    }
    ((float4*)out)[i] = s;
}

extern "C" void kernel_launch(void* const* d_in, const int* in_sizes, int n_in,
                              void* d_out, int out_size) {
    const float* x    = (const float*)d_in[0];  // attn_norm (1,1,32,4096)
    const float* wqkv = (const float*)d_in[1];  // (4096, 6144)
    const float* wo   = (const float*)d_in[2];  // (4096, 4096)
    const float* rot  = (const float*)d_in[3];  // (128, 128)
    const float* ck   = (const float*)d_in[4];  // (32,8,4096,128)
    const float* cv   = (const float*)d_in[5];  // (32,8,4096,128)
    const int*   curp = (const int*)d_in[6];    // current_pos (low 32 bits)
    float* out = (float*)d_out;

    void *p1, *p2, *attnp;
    cudaGetSymbolAddress(&p1, g_part1);
    cudaGetSymbolAddress(&p2, g_part2);
    cudaGetSymbolAddress(&attnp, g_attn);

    // three no-ops: keep the qkv GEMM in the ncu-profiled 4th launch slot
    k_dummy<<<1, 32>>>();
    k_dummy<<<1, 32>>>();
    k_dummy<<<1, 32>>>();
    k_gemm_part<QKVC><<<dim3(QKVC / 512, KSPLIT), 256>>>(x, wqkv, (float*)p1);
    k_reduce_rope<<<BB * 48, 128>>>(rot);
    k_attn_part<<<dim3(BB * NKV, NSPLIT), 256>>>(ck, cv, curp);
    k_combine<<<BB * NKV, 128>>>(curp);
    k_gemm_part<DIM><<<dim3(DIM / 512, KSPLIT), 256>>>((const float*)attnp, wo, (float*)p2);
    k_out_reduce<<<BB * DIM / 4 / 256, 256>>>(out);
}

// round 13
// speedup vs baseline: 1.4097x; 1.4097x over previous
#include <cuda_runtime.h>
#include <cuda_bf16.h>
#include <math.h>
#include <stdint.h>

#define BB 32
#define DIM 4096
#define NH 32
#define NKV 8
#define GQ 4
#define HD 128
#define KVLEN 4096
#define QKVC 6144          // (NH + 2*NKV) * HD
#define CHUNK 256          // KV positions per attention split
#define NSPLIT 16          // KVLEN / CHUNK

#define MM_KSPL 4          // K split for mma GEMMs
#define MM_KC (DIM / MM_KSPL)
#define CHK 64             // K per smem chunk
#define NCHK (MM_KC / CHK) // 16

// packed fp32x2 FMA (sm_100+)
#define FMA_F32X2(d, a, b, c) \
    asm("fma.rn.f32x2 %0, %1, %2, %3;" : "=l"(d) : "l"(a), "l"(b), "l"(c))

// ---------------- scratch (no allocs allowed) ----------------
__device__ float g_mmq[MM_KSPL][BB][QKVC];      // qkv gemm partials
__device__ float g_mmo[MM_KSPL][BB][DIM];       // out gemm partials
__device__ __nv_bfloat16 g_xh[BB * DIM];        // x hi
__device__ __nv_bfloat16 g_xl[BB * DIM];        // x lo
__device__ __nv_bfloat16 g_ah[BB * DIM];        // attn hi
__device__ __nv_bfloat16 g_al[BB * DIM];        // attn lo
__device__ float g_q[BB * NH * HD];             // rope'd q
__device__ float g_knew[BB * NKV * HD];         // rope'd new k
__device__ float g_vnew[BB * NKV * HD];         // new v
__device__ float g_pm[BB * NKV * NSPLIT * GQ];  // partial max
__device__ float g_ps[BB * NKV * NSPLIT * GQ];  // partial sumexp
__device__ float g_pacc[BB * NKV * NSPLIT * GQ * HD]; // partial weighted V
__device__ float g_attn[BB * DIM];              // attention output (pre-wo)

// ---------------- m16n8k16 bf16 mma (base ISA, works on compute_103) -------
__device__ __forceinline__ void mma16816(float* d, const uint32_t* a,
                                         const uint32_t* b) {
    asm volatile(
        "mma.sync.aligned.m16n8k16.row.col.f32.bf16.bf16.f32 "
        "{%0,%1,%2,%3}, {%4,%5,%6,%7}, {%8,%9}, {%0,%1,%2,%3};\n"
        : "+f"(d[0]), "+f"(d[1]), "+f"(d[2]), "+f"(d[3])
        : "r"(a[0]), "r"(a[1]), "r"(a[2]), "r"(a[3]), "r"(b[0]), "r"(b[1]));
}

// ---------------- hi/lo bf16 split of a 32x4096 fp32 matrix ----------------
__global__ void __launch_bounds__(256) k_split(const float* __restrict__ src,
                                               __nv_bfloat16* __restrict__ h,
                                               __nv_bfloat16* __restrict__ l) {
    int i = (blockIdx.x * 256 + threadIdx.x) * 4;
    float4 v = *(const float4*)(src + i);
    uint32_t h01, h23, l01, l23;
    asm("cvt.rn.satfinite.bf16x2.f32 %0, %1, %2;" : "=r"(h01) : "f"(v.y), "f"(v.x));
    asm("cvt.rn.satfinite.bf16x2.f32 %0, %1, %2;" : "=r"(h23) : "f"(v.w), "f"(v.z));
    float r0 = v.x - __uint_as_float(h01 << 16);
    float r1 = v.y - __uint_as_float(h01 & 0xffff0000u);
    float r2 = v.z - __uint_as_float(h23 << 16);
    float r3 = v.w - __uint_as_float(h23 & 0xffff0000u);
    asm("cvt.rn.satfinite.bf16x2.f32 %0, %1, %2;" : "=r"(l01) : "f"(r1), "f"(r0));
    asm("cvt.rn.satfinite.bf16x2.f32 %0, %1, %2;" : "=r"(l23) : "f"(r3), "f"(r2));
    *(uint2*)((char*)h + (size_t)i * 2) = make_uint2(h01, h23);
    *(uint2*)((char*)l + (size_t)i * 2) = make_uint2(l01, l23);
}

// ---------------- mma.sync GEMM: D[32, COLS] = x @ W, bf16x3 ----------------
// grid (COLS/128, MM_KSPL), block 256 (8 warps, 16 cols each).
// W fp32 streamed via depth-32 reg prefetch -> bf16 hi/lo transposed smem.
template <int COLS>
__global__ void __launch_bounds__(256)
k_mm(const float* __restrict__ w,
     const __nv_bfloat16* __restrict__ xh,
     const __nv_bfloat16* __restrict__ xl,
     float* __restrict__ part) {
    __shared__ __nv_bfloat16 xs_h[32][72], xs_l[32][72];    // x tile  (pad 72)
    __shared__ __nv_bfloat16 ws_h[128][72], ws_l[128][72];  // W^T tile (pad 72)

    const int t = threadIdx.x;
    const int wid = t >> 5, lane = t & 31;
    const int g = lane >> 2, tid4 = lane & 3;
    const int c0 = blockIdx.x * 128;
    const int k0 = blockIdx.y * MM_KC;
    const int m = t & 127;   // W column handled by this thread
    const int kh = t >> 7;   // which 32-k half of the 64-k chunk

    float acc[2][2][4];
#pragma unroll
    for (int a = 0; a < 2; a++)
#pragma unroll
        for (int b = 0; b < 2; b++)
#pragma unroll
            for (int r = 0; r < 4; r++) acc[a][b][r] = 0.f;

    float wreg[32];
    uint32_t xrh[4], xrl[4];
    {   // prologue: prefetch chunk 0
        const float* wp = w + (size_t)(k0 + kh * 32) * COLS + (c0 + m);
#pragma unroll
        for (int j = 0; j < 32; j++) wreg[j] = wp[(size_t)j * COLS];
#pragma unroll
        for (int e = 0; e < 4; e++) {
            int u = t * 4 + e, n = u >> 5, un = u & 31;
            size_t el = (size_t)n * DIM + k0 + un * 2;
            xrh[e] = *(const uint32_t*)((const char*)xh + el * 2);
            xrl[e] = *(const uint32_t*)((const char*)xl + el * 2);
        }
    }

    for (int i = 0; i < NCHK; i++) {
        // convert + store W chunk: ws[col][k] (transposed, hi/lo)
#pragma unroll
        for (int j = 0; j < 32; j += 2) {
            float f0 = wreg[j], f1 = wreg[j + 1];
            uint32_t hi2, lo2;
            asm("cvt.rn.satfinite.bf16x2.f32 %0, %1, %2;" : "=r"(hi2) : "f"(f1), "f"(f0));
            float l0f = f0 - __uint_as_float(hi2 << 16);
            float l1f = f1 - __uint_as_float(hi2 & 0xffff0000u);
            asm("cvt.rn.satfinite.bf16x2.f32 %0, %1, %2;" : "=r"(lo2) : "f"(l1f), "f"(l0f));
            *(uint32_t*)&ws_h[m][kh * 32 + j] = hi2;
            *(uint32_t*)&ws_l[m][kh * 32 + j] = lo2;
        }
        // store x tile
#pragma unroll
        for (int e = 0; e < 4; e++) {
            int u = t * 4 + e, n = u >> 5, un = u & 31;
            *(uint32_t*)&xs_h[n][un * 2] = xrh[e];
            *(uint32_t*)&xs_l[n][un * 2] = xrl[e];
        }
        __syncthreads();

        if (i + 1 < NCHK) {  // prefetch next chunk (overlaps the MMAs below)
            const int kk = k0 + (i + 1) * CHK;
            const float* wp = w + (size_t)(kk + kh * 32) * COLS + (c0 + m);
#pragma unroll
            for (int j = 0; j < 32; j++) wreg[j] = wp[(size_t)j * COLS];
#pragma unroll
            for (int e = 0; e < 4; e++) {
                int u = t * 4 + e, n = u >> 5, un = u & 31;
                size_t el = (size_t)n * DIM + kk + un * 2;
                xrh[e] = *(const uint32_t*)((const char*)xh + el * 2);
                xrl[e] = *(const uint32_t*)((const char*)xl + el * 2);
            }
        }

        // ---- MMAs over the 4 k16-steps of this chunk ----
#pragma unroll
        for (int ks = 0; ks < 4; ks++) {
            uint32_t ah[2][4], al[2][4];
#pragma unroll
            for (int mb = 0; mb < 2; mb++)
#pragma unroll
                for (int r = 0; r < 4; r++) {
                    int row = mb * 16 + g + (r & 1) * 8;
                    int k = ks * 16 + tid4 * 2 + (r >> 1) * 8;
                    ah[mb][r] = *(const uint32_t*)&xs_h[row][k];
                    al[mb][r] = *(const uint32_t*)&xs_l[row][k];
                }
            uint32_t bh[2][2], bl[2][2];
#pragma unroll
            for (int nb = 0; nb < 2; nb++)
#pragma unroll
                for (int r = 0; r < 2; r++) {
                    int col = wid * 16 + nb * 8 + g;
                    int k = ks * 16 + tid4 * 2 + r * 8;
                    bh[nb][r] = *(const uint32_t*)&ws_h[col][k];
                    bl[nb][r] = *(const uint32_t*)&ws_l[col][k];
                }
#pragma unroll
            for (int mb = 0; mb < 2; mb++)
#pragma unroll
                for (int nb = 0; nb < 2; nb++) {
                    mma16816(acc[mb][nb], ah[mb], bh[nb]);
                    mma16816(acc[mb][nb], ah[mb], bl[nb]);
                    mma16816(acc[mb][nb], al[mb], bh[nb]);
                }
        }
        __syncthreads();
    }

    // epilogue: C frag rows = batch, cols = output columns
#pragma unroll
    for (int mb = 0; mb < 2; mb++)
#pragma unroll
        for (int nb = 0; nb < 2; nb++) {
            int row0 = mb * 16 + g;
            int col = wid * 16 + nb * 8 + tid4 * 2;
            float* p0 = part + (size_t)(blockIdx.y * BB + row0) * COLS + c0 + col;
            *(float2*)p0 = make_float2(acc[mb][nb][0], acc[mb][nb][1]);
            float* p1 = part + (size_t)(blockIdx.y * BB + row0 + 8) * COLS + c0 + col;
            *(float2*)p1 = make_float2(acc[mb][nb][2], acc[mb][nb][3]);
        }
}

// ---------------- reduce qkv partials + rope ----------------
__global__ void __launch_bounds__(128) k_reduce_rope(const float* __restrict__ rot) {
    const int b = blockIdx.x / 48;
    const int h = blockIdx.x % 48;
    const int t = threadIdx.x;
    float s = 0.f;
#pragma unroll
    for (int p = 0; p < MM_KSPL; p++) s += g_mmq[p][b][h * HD + t];
    if (h >= 40) {  // v: no rope
        g_vnew[(b * NKV + (h - 40)) * HD + t] = s;
        return;
    }
    __shared__ float vsh[HD];
    vsh[t] = s;
    __syncthreads();
    float o = 0.f;
#pragma unroll 8
    for (int d = 0; d < HD; d++) o = fmaf(vsh[d], rot[d * HD + t], o);
    if (h < 32)
        g_q[(b * NH + h) * HD + t] = o;
    else
        g_knew[(b * NKV + (h - 32)) * HD + t] = o;
}

__global__ void k_dummy() {}

// ---------------- flash-decode partial attention (R7, measured 143us) ----------------
__global__ void __launch_bounds__(256) k_attn_part(const float* __restrict__ ck,
                                                   const float* __restrict__ cv,
                                                   const int* __restrict__ curp) {
    const int bk = blockIdx.x;
    const int b = bk >> 3, kv = bk & 7;
    const int sp = blockIdx.y;
    const int cur = *curp;
    const int L = cur + 1;
    const int s0 = sp * CHUNK;
    const int scnt = min(CHUNK, L - s0);
    if (scnt <= 0) return;
    const int pbase = (bk * NSPLIT + sp) * GQ;
    const int t = threadIdx.x;
    const bool has_cur = (s0 + CHUNK >= L);

    __shared__ float4 sc4[CHUNK];
    __shared__ float4 qsh[GQ][HD / 4];
    __shared__ float red[8];
    __shared__ float mh[GQ], sumh[GQ];
    __shared__ float vred[GQ][HD];

    ((float2*)qsh)[t] = ((const float2*)(g_q + (b * NH + kv * GQ) * HD))[t];
    __syncthreads();

    const float scale = 0.08838834764831845f;
    const float* kbase = ck + (size_t)(b * NKV + kv) * KVLEN * HD;

    {
        const int lane = t & 31, w = t >> 5;
        const int d8 = lane & 7;
        const int r4 = lane >> 3;
        for (int g = w; g < CHUNK / 4; g += 8) {
            const int s = g * 4 + r4;
            const bool act = (s < scnt);
            ulonglong2 k4[4];
#pragma unroll
            for (int j = 0; j < 4; j++) { k4[j].x = 0ull; k4[j].y = 0ull; }
            if (act) {
                const ulonglong2* kr = (has_cur && s == scnt - 1)
                    ? (const ulonglong2*)(g_knew + (b * NKV + kv) * HD)
                    : (const ulonglong2*)(kbase + (size_t)(s0 + s) * HD);
#pragma unroll
                for (int j = 0; j < 4; j++) k4[j] = kr[d8 + 8 * j];
            }
            unsigned long long acc[4] = {0ull, 0ull, 0ull, 0ull};
#pragma unroll
            for (int j = 0; j < 4; j++) {
#pragma unroll
                for (int h = 0; h < 4; h++) {
                    ulonglong2 q2 = ((const ulonglong2*)qsh[h])[d8 + 8 * j];
                    FMA_F32X2(acc[h], k4[j].x, q2.x, acc[h]);
                    FMA_F32X2(acc[h], k4[j].y, q2.y, acc[h]);
                }
            }
            float r[4];
#pragma unroll
            for (int h = 0; h < 4; h++) {
                float lo, hi;
                asm("mov.b64 {%0, %1}, %2;" : "=f"(lo), "=f"(hi) : "l"(acc[h]));
                r[h] = lo + hi;
            }
#pragma unroll
            for (int o = 1; o <= 4; o <<= 1) {
#pragma unroll
                for (int h = 0; h < 4; h++)
                    r[h] += __shfl_xor_sync(0xffffffffu, r[h], o);
            }
            if (act && d8 == 0)
                sc4[s] = make_float4(r[0] * scale, r[1] * scale,
                                     r[2] * scale, r[3] * scale);
        }
    }
    __syncthreads();

    {
        const int h = t >> 6, l64 = t & 63, wid = t >> 5, lane = t & 31;
        const float* schf = (const float*)sc4;
        float lm = -INFINITY;
        for (int s = l64; s < scnt; s += 64) lm = fmaxf(lm, schf[s * 4 + h]);
#pragma unroll
        for (int o = 16; o > 0; o >>= 1) lm = fmaxf(lm, __shfl_xor_sync(0xffffffffu, lm, o));
        if (lane == 0) red[wid] = lm;
        __syncthreads();
        if (l64 == 0) mh[h] = fmaxf(red[2 * h], red[2 * h + 1]);
        __syncthreads();
        const float m = mh[h];
        float ls = 0.f;
        float* scw = (float*)sc4;
        for (int s = l64; s < scnt; s += 64) {
            float p = __expf(scw[s * 4 + h] - m);
            scw[s * 4 + h] = p;
            ls += p;
        }
#pragma unroll
        for (int o = 16; o > 0; o >>= 1) ls += __shfl_xor_sync(0xffffffffu, ls, o);
        if (lane == 0) red[wid] = ls;
        __syncthreads();
        if (l64 == 0) sumh[h] = red[2 * h] + red[2 * h + 1];
    }
    __syncthreads();

    {
        const int d = t & 127, half = t >> 7;
        unsigned long long a01 = 0ull, a23 = 0ull;
        const float* vbase = cv + ((size_t)(b * NKV + kv) * KVLEN + s0) * HD + d;
        const int slim = scnt - (has_cur ? 1 : 0);
#pragma unroll 8
        for (int s = half; s < slim; s += 2) {
            float vv = vbase[(size_t)s * HD];
            ulonglong2 p = ((const ulonglong2*)sc4)[s];
            unsigned long long v2;
            asm("mov.b64 %0, {%1, %1};" : "=l"(v2) : "f"(vv));
            FMA_F32X2(a01, p.x, v2, a01);
            FMA_F32X2(a23, p.y, v2, a23);
        }
        if (has_cur && ((scnt - 1) & 1) == half) {
            const int s = scnt - 1;
            float vv = g_vnew[(b * NKV + kv) * HD + d];
            ulonglong2 p = ((const ulonglong2*)sc4)[s];
            unsigned long long v2;
            asm("mov.b64 %0, {%1, %1};" : "=l"(v2) : "f"(vv));
            FMA_F32X2(a01, p.x, v2, a01);
            FMA_F32X2(a23, p.y, v2, a23);
        }
        float a0, a1, a2, a3;
        asm("mov.b64 {%0, %1}, %2;" : "=f"(a0), "=f"(a1) : "l"(a01));
        asm("mov.b64 {%0, %1}, %2;" : "=f"(a2), "=f"(a3) : "l"(a23));
        if (half == 1) {
            vred[0][d] = a0; vred[1][d] = a1; vred[2][d] = a2; vred[3][d] = a3;
        }
        __syncthreads();
        if (half == 0) {
            g_pacc[(pbase + 0) * HD + d] = a0 + vred[0][d];
            g_pacc[(pbase + 1) * HD + d] = a1 + vred[1][d];
            g_pacc[(pbase + 2) * HD + d] = a2 + vred[2][d];
            g_pacc[(pbase + 3) * HD + d] = a3 + vred[3][d];
        }
        if (t < GQ) {
            g_pm[pbase + t] = mh[t];
            g_ps[pbase + t] = sumh[t];
        }
    }
}

// ---------------- LSE merge across splits ----------------
__global__ void __launch_bounds__(128) k_combine(const int* __restrict__ curp) {
    const int bk = blockIdx.x;
    const int b = bk >> 3, kv = bk & 7;
    const int t = threadIdx.x;
    const int h = t >> 5, d4 = t & 31;
    const int nsp = (*curp + CHUNK) / CHUNK;

    __shared__ float esh[GQ][NSPLIT];
    __shared__ float dens[GQ];
    if (d4 == 0) {
        float m = -INFINITY;
        for (int sp = 0; sp < nsp; sp++)
            m = fmaxf(m, g_pm[(bk * NSPLIT + sp) * GQ + h]);
        float den = 0.f;
        for (int sp = 0; sp < nsp; sp++) {
            float e = __expf(g_pm[(bk * NSPLIT + sp) * GQ + h] - m);
            esh[h][sp] = e;
            den += g_ps[(bk * NSPLIT + sp) * GQ + h] * e;
        }
        dens[h] = den;
    }
    __syncthreads();
    float4 num = make_float4(0.f, 0.f, 0.f, 0.f);
#pragma unroll 4
    for (int sp = 0; sp < nsp; sp++) {
        const float4* pa = (const float4*)(g_pacc + ((bk * NSPLIT + sp) * GQ + h) * HD);
        float4 v = pa[d4];
        float e = esh[h][sp];
        num.x = fmaf(v.x, e, num.x); num.y = fmaf(v.y, e, num.y);
        num.z = fmaf(v.z, e, num.z); num.w = fmaf(v.w, e, num.w);
    }
    const float inv = 1.0f / dens[h];
    float4* o = (float4*)(g_attn + (b * NH + kv * GQ + h) * HD);
    o[d4] = make_float4(num.x * inv, num.y * inv, num.z * inv, num.w * inv);
}

// ---------------- final reduce of wo partials ----------------
__global__ void __launch_bounds__(256) k_out_reduce(float* __restrict__ out) {
    const int i = blockIdx.x * 256 + threadIdx.x;  // float4 index
    const float4* p2 = (const float4*)g_mmo;
    float4 s = make_float4(0.f, 0.f, 0.f, 0.f);
#pragma unroll
    for (int p = 0; p < MM_KSPL; p++) {
        float4 v = p2[(size_t)p * (BB * DIM / 4) + i];
        s.x += v.x; s.y += v.y; s.z += v.z; s.w += v.w;
    }
    ((float4*)out)[i] = s;
}

extern "C" void kernel_launch(void* const* d_in, const int* in_sizes, int n_in,
                              void* d_out, int out_size) {
    const float* x    = (const float*)d_in[0];
    const float* wqkv = (const float*)d_in[1];
    const float* wo   = (const float*)d_in[2];
    const float* rot  = (const float*)d_in[3];
    const float* ck   = (const float*)d_in[4];
    const float* cv   = (const float*)d_in[5];
    const int*   curp = (const int*)d_in[6];
    float* out = (float*)d_out;

    void *mmq, *mmo, *xh, *xl, *ah, *al, *attnp;
    cudaGetSymbolAddress(&mmq, g_mmq);
    cudaGetSymbolAddress(&mmo, g_mmo);
    cudaGetSymbolAddress(&xh, g_xh);
    cudaGetSymbolAddress(&xl, g_xl);
    cudaGetSymbolAddress(&ah, g_ah);
    cudaGetSymbolAddress(&al, g_al);
    cudaGetSymbolAddress(&attnp, g_attn);

    k_split<<<BB * DIM / 4 / 256, 256>>>(x, (__nv_bfloat16*)xh, (__nv_bfloat16*)xl);
    k_dummy<<<1, 32>>>();  // slot shift: k_mm<QKVC> lands in profiled launch 4
    k_dummy<<<1, 32>>>();
    k_mm<QKVC><<<dim3(QKVC / 128, MM_KSPL), 256>>>(
        wqkv, (const __nv_bfloat16*)xh, (const __nv_bfloat16*)xl, (float*)mmq);
    k_reduce_rope<<<BB * 48, 128>>>(rot);
    k_attn_part<<<dim3(BB * NKV, NSPLIT), 256>>>(ck, cv, curp);
    k_combine<<<BB * NKV, 128>>>(curp);
    k_split<<<BB * DIM / 4 / 256, 256>>>((const float*)attnp,
                                         (__nv_bfloat16*)ah, (__nv_bfloat16*)al);
    k_mm<DIM><<<dim3(DIM / 128, MM_KSPL), 256>>>(
        wo, (const __nv_bfloat16*)ah, (const __nv_bfloat16*)al, (float*)mmo);
    k_out_reduce<<<BB * DIM / 4 / 256, 256>>>(out);
}

// round 15
// speedup vs baseline: 1.6375x; 1.1616x over previous
#include <cuda_runtime.h>
#include <cuda_bf16.h>
#include <math.h>
#include <stdint.h>

#define BB 32
#define DIM 4096
#define NH 32
#define NKV 8
#define GQ 4
#define HD 128
#define KVLEN 4096
#define QKVC 6144          // (NH + 2*NKV) * HD
#define CHUNK 256          // KV positions per attention split
#define NSPLIT 16          // KVLEN / CHUNK

#define MM_KSPL 8          // K split for mma GEMMs
#define MM_KC (DIM / MM_KSPL)
#define CHK 64             // K per smem chunk
#define NCHK (MM_KC / CHK) // 8

// packed fp32x2 FMA (sm_100+)
#define FMA_F32X2(d, a, b, c) \
    asm("fma.rn.f32x2 %0, %1, %2, %3;" : "=l"(d) : "l"(a), "l"(b), "l"(c))

// ---------------- scratch (no allocs allowed) ----------------
__device__ float g_mmq[MM_KSPL][BB][QKVC];      // qkv gemm partials
__device__ float g_mmo[MM_KSPL][BB][DIM];       // out gemm partials
__device__ __nv_bfloat16 g_xh[BB * DIM];        // x hi
__device__ __nv_bfloat16 g_xl[BB * DIM];        // x lo
__device__ __nv_bfloat16 g_ah[BB * DIM];        // attn hi
__device__ __nv_bfloat16 g_al[BB * DIM];        // attn lo
__device__ float g_q[BB * NH * HD];             // rope'd q
__device__ float g_knew[BB * NKV * HD];         // rope'd new k
__device__ float g_vnew[BB * NKV * HD];         // new v
__device__ float g_pm[BB * NKV * NSPLIT * GQ];  // partial max
__device__ float g_ps[BB * NKV * NSPLIT * GQ];  // partial sumexp
__device__ float g_pacc[BB * NKV * NSPLIT * GQ * HD]; // partial weighted V
__device__ float g_attn[BB * DIM];              // attention output (pre-wo)

// ---------------- m16n8k16 bf16 mma + ldmatrix (base ISA) ----------------
__device__ __forceinline__ void mma16816(float* d, const uint32_t* a,
                                         const uint32_t* b) {
    asm volatile(
        "mma.sync.aligned.m16n8k16.row.col.f32.bf16.bf16.f32 "
        "{%0,%1,%2,%3}, {%4,%5,%6,%7}, {%8,%9}, {%0,%1,%2,%3};\n"
        : "+f"(d[0]), "+f"(d[1]), "+f"(d[2]), "+f"(d[3])
        : "r"(a[0]), "r"(a[1]), "r"(a[2]), "r"(a[3]), "r"(b[0]), "r"(b[1]));
}
__device__ __forceinline__ void ldsm_x4(uint32_t* r, uint32_t saddr) {
    asm volatile("ldmatrix.sync.aligned.m8n8.x4.shared.b16 {%0,%1,%2,%3}, [%4];"
                 : "=r"(r[0]), "=r"(r[1]), "=r"(r[2]), "=r"(r[3]) : "r"(saddr));
}

// ---------------- hi/lo bf16 split of a 32x4096 fp32 matrix ----------------
__global__ void __launch_bounds__(256) k_split(const float* __restrict__ src,
                                               __nv_bfloat16* __restrict__ h,
                                               __nv_bfloat16* __restrict__ l) {
    int i = (blockIdx.x * 256 + threadIdx.x) * 4;
    float4 v = *(const float4*)(src + i);
    uint32_t h01, h23, l01, l23;
    asm("cvt.rn.satfinite.bf16x2.f32 %0, %1, %2;" : "=r"(h01) : "f"(v.y), "f"(v.x));
    asm("cvt.rn.satfinite.bf16x2.f32 %0, %1, %2;" : "=r"(h23) : "f"(v.w), "f"(v.z));
    float r0 = v.x - __uint_as_float(h01 << 16);
    float r1 = v.y - __uint_as_float(h01 & 0xffff0000u);
    float r2 = v.z - __uint_as_float(h23 << 16);
    float r3 = v.w - __uint_as_float(h23 & 0xffff0000u);
    asm("cvt.rn.satfinite.bf16x2.f32 %0, %1, %2;" : "=r"(l01) : "f"(r1), "f"(r0));
    asm("cvt.rn.satfinite.bf16x2.f32 %0, %1, %2;" : "=r"(l23) : "f"(r3), "f"(r2));
    *(uint2*)((char*)h + (size_t)i * 2) = make_uint2(h01, h23);
    *(uint2*)((char*)l + (size_t)i * 2) = make_uint2(l01, l23);
}

// ---------------- mma.sync GEMM: D[32, COLS] = x @ W, bf16x3 ----------------
// grid (COLS/128, MM_KSPL), block 256 (8 warps, 16 cols each).
// Fragments via ldmatrix; staging via STS.128/LDG.128.
template <int COLS>
__global__ void __launch_bounds__(256)
k_mm(const float* __restrict__ w,
     const __nv_bfloat16* __restrict__ xh,
     const __nv_bfloat16* __restrict__ xl,
     float* __restrict__ part) {
    __shared__ __nv_bfloat16 xs_h[32][72], xs_l[32][72];    // x tile  (pad 72)
    __shared__ __nv_bfloat16 ws_h[128][72], ws_l[128][72];  // W^T tile (pad 72)

    const int t = threadIdx.x;
    const int wid = t >> 5, lane = t & 31;
    const int g = lane >> 2, tid4 = lane & 3;
    const int c0 = blockIdx.x * 128;
    const int k0 = blockIdx.y * MM_KC;
    const int m = t & 127;   // W column handled by this thread
    const int kh = t >> 7;   // which 32-k half of the 64-k chunk

    // ldmatrix lane address components (constant per thread)
    const int lrowA = (lane & 7) + ((lane >> 3) & 1) * 8;  // row-in-16 for A
    const int lkgA = lane >> 4;                            // k-group for A
    const int lmB = lane >> 3;                             // matrix idx for B x4
    const int lrowB = wid * 16 + (lmB >> 1) * 8 + (lane & 7);
    const int lkgB = lmB & 1;

    float acc[2][2][4];
#pragma unroll
    for (int a = 0; a < 2; a++)
#pragma unroll
        for (int b = 0; b < 2; b++)
#pragma unroll
            for (int r = 0; r < 4; r++) acc[a][b][r] = 0.f;

    const int xn = (t * 4) >> 5;        // x row staged by this thread
    const int xu = (t * 4) & 31;        // 2-bf16 unit base
    float wreg[32];
    uint4 xrh, xrl;
    {   // prologue: prefetch chunk 0
        const float* wp = w + (size_t)(k0 + kh * 32) * COLS + (c0 + m);
#pragma unroll
        for (int j = 0; j < 32; j++) wreg[j] = wp[(size_t)j * COLS];
        size_t el = (size_t)xn * DIM + k0 + xu * 2;
        xrh = *(const uint4*)((const char*)xh + el * 2);
        xrl = *(const uint4*)((const char*)xl + el * 2);
    }

    for (int i = 0; i < NCHK; i++) {
        // convert + store W chunk: ws[col][k], STS.128
#pragma unroll
        for (int j = 0; j < 32; j += 8) {
            uint4 hv, lv;
            uint32_t* hp = (uint32_t*)&hv;
            uint32_t* lp = (uint32_t*)&lv;
#pragma unroll
            for (int e = 0; e < 4; e++) {
                float f0 = wreg[j + 2 * e], f1 = wreg[j + 2 * e + 1];
                uint32_t hi2, lo2;
                asm("cvt.rn.satfinite.bf16x2.f32 %0, %1, %2;" : "=r"(hi2) : "f"(f1), "f"(f0));
                float l0f = f0 - __uint_as_float(hi2 << 16);
                float l1f = f1 - __uint_as_float(hi2 & 0xffff0000u);
                asm("cvt.rn.satfinite.bf16x2.f32 %0, %1, %2;" : "=r"(lo2) : "f"(l1f), "f"(l0f));
                hp[e] = hi2;
                lp[e] = lo2;
            }
            *(uint4*)&ws_h[m][kh * 32 + j] = hv;
            *(uint4*)&ws_l[m][kh * 32 + j] = lv;
        }
        // store x tile (STS.128)
        *(uint4*)&xs_h[xn][xu * 2] = xrh;
        *(uint4*)&xs_l[xn][xu * 2] = xrl;
        __syncthreads();

        if (i + 1 < NCHK) {  // prefetch next chunk (overlaps MMAs)
            const int kk = k0 + (i + 1) * CHK;
            const float* wp = w + (size_t)(kk + kh * 32) * COLS + (c0 + m);
#pragma unroll
            for (int j = 0; j < 32; j++) wreg[j] = wp[(size_t)j * COLS];
            size_t el = (size_t)xn * DIM + kk + xu * 2;
            xrh = *(const uint4*)((const char*)xh + el * 2);
            xrl = *(const uint4*)((const char*)xl + el * 2);
        }

        // ---- MMAs over the 4 k16-steps of this chunk ----
#pragma unroll
        for (int ks = 0; ks < 4; ks++) {
            uint32_t ah[2][4], al[2][4];
#pragma unroll
            for (int mb = 0; mb < 2; mb++) {
                uint32_t sa_h = (uint32_t)__cvta_generic_to_shared(
                    &xs_h[mb * 16 + lrowA][ks * 16 + lkgA * 8]);
                ldsm_x4(ah[mb], sa_h);
                uint32_t sa_l = (uint32_t)__cvta_generic_to_shared(
                    &xs_l[mb * 16 + lrowA][ks * 16 + lkgA * 8]);
                ldsm_x4(al[mb], sa_l);
            }
            uint32_t bh4[4], bl4[4];
            {
                uint32_t sb_h = (uint32_t)__cvta_generic_to_shared(
                    &ws_h[lrowB][ks * 16 + lkgB * 8]);
                ldsm_x4(bh4, sb_h);
                uint32_t sb_l = (uint32_t)__cvta_generic_to_shared(
                    &ws_l[lrowB][ks * 16 + lkgB * 8]);
                ldsm_x4(bl4, sb_l);
            }
            // bh4 = {nb0k0, nb0k8, nb1k0, nb1k8}
#pragma unroll
            for (int mb = 0; mb < 2; mb++)
#pragma unroll
                for (int nb = 0; nb < 2; nb++) {
                    mma16816(acc[mb][nb], ah[mb], &bh4[nb * 2]);
                    mma16816(acc[mb][nb], ah[mb], &bl4[nb * 2]);
                    mma16816(acc[mb][nb], al[mb], &bh4[nb * 2]);
                }
        }
        __syncthreads();
    }

    // epilogue: C frag rows = batch, cols = output columns
#pragma unroll
    for (int mb = 0; mb < 2; mb++)
#pragma unroll
        for (int nb = 0; nb < 2; nb++) {
            int row0 = mb * 16 + g;
            int col = wid * 16 + nb * 8 + tid4 * 2;
            float* p0 = part + (size_t)(blockIdx.y * BB + row0) * COLS + c0 + col;
            *(float2*)p0 = make_float2(acc[mb][nb][0], acc[mb][nb][1]);
            float* p1 = part + (size_t)(blockIdx.y * BB + row0 + 8) * COLS + c0 + col;
            *(float2*)p1 = make_float2(acc[mb][nb][2], acc[mb][nb][3]);
        }
}

// ---------------- reduce qkv partials + rope ----------------
__global__ void __launch_bounds__(128) k_reduce_rope(const float* __restrict__ rot) {
    const int b = blockIdx.x / 48;
    const int h = blockIdx.x % 48;
    const int t = threadIdx.x;
    float s = 0.f;
#pragma unroll
    for (int p = 0; p < MM_KSPL; p++) s += g_mmq[p][b][h * HD + t];
    if (h >= 40) {  // v: no rope
        g_vnew[(b * NKV + (h - 40)) * HD + t] = s;
        return;
    }
    __shared__ float vsh[HD];
    vsh[t] = s;
    __syncthreads();
    float o = 0.f;
#pragma unroll 8
    for (int d = 0; d < HD; d++) o = fmaf(vsh[d], rot[d * HD + t], o);
    if (h < 32)
        g_q[(b * NH + h) * HD + t] = o;
    else
        g_knew[(b * NKV + (h - 32)) * HD + t] = o;
}

__global__ void k_dummy() {}

// ---------------- flash-decode partial attention (R7, measured 143us) ----------------
__global__ void __launch_bounds__(256) k_attn_part(const float* __restrict__ ck,
                                                   const float* __restrict__ cv,
                                                   const int* __restrict__ curp) {
    const int bk = blockIdx.x;
    const int b = bk >> 3, kv = bk & 7;
    const int sp = blockIdx.y;
    const int cur = *curp;
    const int L = cur + 1;
    const int s0 = sp * CHUNK;
    const int scnt = min(CHUNK, L - s0);
    if (scnt <= 0) return;
    const int pbase = (bk * NSPLIT + sp) * GQ;
    const int t = threadIdx.x;
    const bool has_cur = (s0 + CHUNK >= L);

    __shared__ float4 sc4[CHUNK];
    __shared__ float4 qsh[GQ][HD / 4];
    __shared__ float red[8];
    __shared__ float mh[GQ], sumh[GQ];
    __shared__ float vred[GQ][HD];

    ((float2*)qsh)[t] = ((const float2*)(g_q + (b * NH + kv * GQ) * HD))[t];
    __syncthreads();

    const float scale = 0.08838834764831845f;
    const float* kbase = ck + (size_t)(b * NKV + kv) * KVLEN * HD;

    {
        const int lane = t & 31, w = t >> 5;
        const int d8 = lane & 7;
        const int r4 = lane >> 3;
        for (int g = w; g < CHUNK / 4; g += 8) {
            const int s = g * 4 + r4;
            const bool act = (s < scnt);
            ulonglong2 k4[4];
#pragma unroll
            for (int j = 0; j < 4; j++) { k4[j].x = 0ull; k4[j].y = 0ull; }
            if (act) {
                const ulonglong2* kr = (has_cur && s == scnt - 1)
                    ? (const ulonglong2*)(g_knew + (b * NKV + kv) * HD)
                    : (const ulonglong2*)(kbase + (size_t)(s0 + s) * HD);
#pragma unroll
                for (int j = 0; j < 4; j++) k4[j] = kr[d8 + 8 * j];
            }
            unsigned long long acc[4] = {0ull, 0ull, 0ull, 0ull};
#pragma unroll
            for (int j = 0; j < 4; j++) {
#pragma unroll
                for (int h = 0; h < 4; h++) {
                    ulonglong2 q2 = ((const ulonglong2*)qsh[h])[d8 + 8 * j];
                    FMA_F32X2(acc[h], k4[j].x, q2.x, acc[h]);
                    FMA_F32X2(acc[h], k4[j].y, q2.y, acc[h]);
                }
            }
            float r[4];
#pragma unroll
            for (int h = 0; h < 4; h++) {
                float lo, hi;
                asm("mov.b64 {%0, %1}, %2;" : "=f"(lo), "=f"(hi) : "l"(acc[h]));
                r[h] = lo + hi;
            }
#pragma unroll
            for (int o = 1; o <= 4; o <<= 1) {
#pragma unroll
                for (int h = 0; h < 4; h++)
                    r[h] += __shfl_xor_sync(0xffffffffu, r[h], o);
            }
            if (act && d8 == 0)
                sc4[s] = make_float4(r[0] * scale, r[1] * scale,
                                     r[2] * scale, r[3] * scale);
        }
    }
    __syncthreads();

    {
        const int h = t >> 6, l64 = t & 63, wid = t >> 5, lane = t & 31;
        const float* schf = (const float*)sc4;
        float lm = -INFINITY;
        for (int s = l64; s < scnt; s += 64) lm = fmaxf(lm, schf[s * 4 + h]);
#pragma unroll
        for (int o = 16; o > 0; o >>= 1) lm = fmaxf(lm, __shfl_xor_sync(0xffffffffu, lm, o));
        if (lane == 0) red[wid] = lm;
        __syncthreads();
        if (l64 == 0) mh[h] = fmaxf(red[2 * h], red[2 * h + 1]);
        __syncthreads();
        const float m = mh[h];
        float ls = 0.f;
        float* scw = (float*)sc4;
        for (int s = l64; s < scnt; s += 64) {
            float p = __expf(scw[s * 4 + h] - m);
            scw[s * 4 + h] = p;
            ls += p;
        }
#pragma unroll
        for (int o = 16; o > 0; o >>= 1) ls += __shfl_xor_sync(0xffffffffu, ls, o);
        if (lane == 0) red[wid] = ls;
        __syncthreads();
        if (l64 == 0) sumh[h] = red[2 * h] + red[2 * h + 1];
    }
    __syncthreads();

    {
        const int d = t & 127, half = t >> 7;
        unsigned long long a01 = 0ull, a23 = 0ull;
        const float* vbase = cv + ((size_t)(b * NKV + kv) * KVLEN + s0) * HD + d;
        const int slim = scnt - (has_cur ? 1 : 0);
#pragma unroll 8
        for (int s = half; s < slim; s += 2) {
            float vv = vbase[(size_t)s * HD];
            ulonglong2 p = ((const ulonglong2*)sc4)[s];
            unsigned long long v2;
            asm("mov.b64 %0, {%1, %1};" : "=l"(v2) : "f"(vv));
            FMA_F32X2(a01, p.x, v2, a01);
            FMA_F32X2(a23, p.y, v2, a23);
        }
        if (has_cur && ((scnt - 1) & 1) == half) {
            const int s = scnt - 1;
            float vv = g_vnew[(b * NKV + kv) * HD + d];
            ulonglong2 p = ((const ulonglong2*)sc4)[s];
            unsigned long long v2;
            asm("mov.b64 %0, {%1, %1};" : "=l"(v2) : "f"(vv));
            FMA_F32X2(a01, p.x, v2, a01);
            FMA_F32X2(a23, p.y, v2, a23);
        }
        float a0, a1, a2, a3;
        asm("mov.b64 {%0, %1}, %2;" : "=f"(a0), "=f"(a1) : "l"(a01));
        asm("mov.b64 {%0, %1}, %2;" : "=f"(a2), "=f"(a3) : "l"(a23));
        if (half == 1) {
            vred[0][d] = a0; vred[1][d] = a1; vred[2][d] = a2; vred[3][d] = a3;
        }
        __syncthreads();
        if (half == 0) {
            g_pacc[(pbase + 0) * HD + d] = a0 + vred[0][d];
            g_pacc[(pbase + 1) * HD + d] = a1 + vred[1][d];
            g_pacc[(pbase + 2) * HD + d] = a2 + vred[2][d];
            g_pacc[(pbase + 3) * HD + d] = a3 + vred[3][d];
        }
        if (t < GQ) {
            g_pm[pbase + t] = mh[t];
            g_ps[pbase + t] = sumh[t];
        }
    }
}

// ---------------- LSE merge across splits ----------------
__global__ void __launch_bounds__(128) k_combine(const int* __restrict__ curp) {
    const int bk = blockIdx.x;
    const int b = bk >> 3, kv = bk & 7;
    const int t = threadIdx.x;
    const int h = t >> 5, d4 = t & 31;
    const int nsp = (*curp + CHUNK) / CHUNK;

    __shared__ float esh[GQ][NSPLIT];
    __shared__ float dens[GQ];
    if (d4 == 0) {
        float m = -INFINITY;
        for (int sp = 0; sp < nsp; sp++)
            m = fmaxf(m, g_pm[(bk * NSPLIT + sp) * GQ + h]);
        float den = 0.f;
        for (int sp = 0; sp < nsp; sp++) {
            float e = __expf(g_pm[(bk * NSPLIT + sp) * GQ + h] - m);
            esh[h][sp] = e;
            den += g_ps[(bk * NSPLIT + sp) * GQ + h] * e;
        }
        dens[h] = den;
    }
    __syncthreads();
    float4 num = make_float4(0.f, 0.f, 0.f, 0.f);
#pragma unroll 4
    for (int sp = 0; sp < nsp; sp++) {
        const float4* pa = (const float4*)(g_pacc + ((bk * NSPLIT + sp) * GQ + h) * HD);
        float4 v = pa[d4];
        float e = esh[h][sp];
        num.x = fmaf(v.x, e, num.x); num.y = fmaf(v.y, e, num.y);
        num.z = fmaf(v.z, e, num.z); num.w = fmaf(v.w, e, num.w);
    }
    const float inv = 1.0f / dens[h];
    float4* o = (float4*)(g_attn + (b * NH + kv * GQ + h) * HD);
    o[d4] = make_float4(num.x * inv, num.y * inv, num.z * inv, num.w * inv);
}

// ---------------- final reduce of wo partials ----------------
__global__ void __launch_bounds__(256) k_out_reduce(float* __restrict__ out) {
    const int i = blockIdx.x * 256 + threadIdx.x;  // float4 index
    const float4* p2 = (const float4*)g_mmo;
    float4 s = make_float4(0.f, 0.f, 0.f, 0.f);
#pragma unroll
    for (int p = 0; p < MM_KSPL; p++) {
        float4 v = p2[(size_t)p * (BB * DIM / 4) + i];
        s.x += v.x; s.y += v.y; s.z += v.z; s.w += v.w;
    }
    ((float4*)out)[i] = s;
}

extern "C" void kernel_launch(void* const* d_in, const int* in_sizes, int n_in,
                              void* d_out, int out_size) {
    const float* x    = (const float*)d_in[0];
    const float* wqkv = (const float*)d_in[1];
    const float* wo   = (const float*)d_in[2];
    const float* rot  = (const float*)d_in[3];
    const float* ck   = (const float*)d_in[4];
    const float* cv   = (const float*)d_in[5];
    const int*   curp = (const int*)d_in[6];
    float* out = (float*)d_out;

    void *mmq, *mmo, *xh, *xl, *ah, *al, *attnp;
    cudaGetSymbolAddress(&mmq, g_mmq);
    cudaGetSymbolAddress(&mmo, g_mmo);
    cudaGetSymbolAddress(&xh, g_xh);
    cudaGetSymbolAddress(&xl, g_xl);
    cudaGetSymbolAddress(&ah, g_ah);
    cudaGetSymbolAddress(&al, g_al);
    cudaGetSymbolAddress(&attnp, g_attn);

    k_split<<<BB * DIM / 4 / 256, 256>>>(x, (__nv_bfloat16*)xh, (__nv_bfloat16*)xl);
    k_dummy<<<1, 32>>>();  // slot shift: k_mm<QKVC> lands in profiled launch 4
    k_dummy<<<1, 32>>>();
    k_mm<QKVC><<<dim3(QKVC / 128, MM_KSPL), 256>>>(
        wqkv, (const __nv_bfloat16*)xh, (const __nv_bfloat16*)xl, (float*)mmq);
    k_reduce_rope<<<BB * 48, 128>>>(rot);
    k_attn_part<<<dim3(BB * NKV, NSPLIT), 256>>>(ck, cv, curp);
    k_combine<<<BB * NKV, 128>>>(curp);
    k_split<<<BB * DIM / 4 / 256, 256>>>((const float*)attnp,
                                         (__nv_bfloat16*)ah, (__nv_bfloat16*)al);
    k_mm<DIM><<<dim3(DIM / 128, MM_KSPL), 256>>>(
        wo, (const __nv_bfloat16*)ah, (const __nv_bfloat16*)al, (float*)mmo);
    k_out_reduce<<<BB * DIM / 4 / 256, 256>>>(out);
}